// round 6
// baseline (speedup 1.0000x reference)
#include <cuda_runtime.h>
#include <math.h>

#define NN 768
#define G 128          // grid blocks (<= SM count, 1 block/SM => co-resident)
#define T 1024         // threads per block (32 warps)

// ---------------- scratch ----------------
__device__ float g_q[64*NN], g_k[64*NN], g_vT[NN*64];
__device__ float g_A[128*NN], g_B[128*NN];
__device__ float2 g_nc1[128], g_nc2[128], g_ncc[128];
__device__ float g_Sq[NN], g_Sk[NN];
__device__ float g_avp[2*64*NN], g_g1[128*NN];
__device__ float g_Wp[128*64], g_bp[128];
__device__ int g_bar_count;
__device__ volatile int g_bar_gen;

// ---------------- grid barrier ----------------
__device__ __forceinline__ void gsync() {
    __threadfence();
    __syncthreads();
    if (threadIdx.x == 0) {
        int gen = g_bar_gen;
        if (atomicAdd(&g_bar_count, 1) == G - 1) {
            g_bar_count = 0;
            __threadfence();
            g_bar_gen = gen + 1;
        } else {
            while (g_bar_gen == gen) __nanosleep(32);
        }
        __threadfence();
    }
    __syncthreads();
}

__device__ __forceinline__ float wsum(float v) {
    #pragma unroll
    for (int o = 16; o; o >>= 1) v += __shfl_xor_sync(0xffffffffu, v, o);
    return v;
}

// ---------------- the single fused kernel ----------------
__global__ void __launch_bounds__(T, 1)
k_fused(const float* __restrict__ desc1, const float* __restrict__ desc2,
        const float* __restrict__ qw, const float* __restrict__ qb,
        const float* __restrict__ kw, const float* __restrict__ kb,
        const float* __restrict__ vw, const float* __restrict__ vbias,
        const float* __restrict__ mhw, const float* __restrict__ mhb,
        const float* __restrict__ cw1, const float* __restrict__ cb1,
        const float* __restrict__ cbg, const float* __restrict__ cbb,
        const float* __restrict__ cw2, const float* __restrict__ cb2,
        const float* __restrict__ shw, const float* __restrict__ shb,
        const float* __restrict__ bn1g, const float* __restrict__ bn1b,
        const float* __restrict__ sw1, const float* __restrict__ sb1,
        const float* __restrict__ bn2g, const float* __restrict__ bn2b,
        const float* __restrict__ sw2, const float* __restrict__ sb2,
        float* __restrict__ out_desc, float* __restrict__ out_score)
{
    __shared__ union {
        struct { float As[4096]; float Bs[4096]; float2 scb[128]; float w2s[128];
                 float Sqs[64]; float Sks[64]; } sc;                       // ~34KB
        struct { float Vs[4096]; float Ps[1024]; float red[1024]; } av;    // 24KB
    } sm;

    const int vb = blockIdx.x;
    const int tid = threadIdx.x;
    const int wid = tid >> 5, lane = tid & 31;
    const int gw = vb * 32 + wid;          // global warp id, 0..4095

    // ===== S1: q/k/v convs (2-row x 32-col units) + fused W' = cw1[:,64:]@mhw, b' =====
    if (gw < 2304) {
        int mat = gw / 768, rem = gw % 768;
        int rp = rem / 24, cb = rem % 24;
        int c = cb * 32 + lane;
        int r0 = rp * 2;
        const float *W, *X, *Bb;
        if (mat == 0)      { W = qw; X = desc1; Bb = qb; }
        else if (mat == 1) { W = kw; X = desc2; Bb = kb; }
        else               { W = vw; X = desc2; Bb = vbias; }
        float a0 = 0.f, a1 = 0.f;
        #pragma unroll 8
        for (int i = 0; i < 64; i++) {
            float x = __ldg(X + i * NN + c);
            a0 = fmaf(__ldg(W + r0 * 64 + i), x, a0);
            a1 = fmaf(__ldg(W + (r0 + 1) * 64 + i), x, a1);
        }
        a0 += __ldg(Bb + r0); a1 += __ldg(Bb + r0 + 1);
        if (mat == 0)      { g_q[r0 * NN + c] = a0; g_q[(r0 + 1) * NN + c] = a1; }
        else if (mat == 1) { g_k[r0 * NN + c] = a0; g_k[(r0 + 1) * NN + c] = a1; }
        else               { *(float2*)&g_vT[c * 64 + r0] = make_float2(a0, a1); }
    } else if (gw < 2560) {
        int u = gw - 2304;                  // W'[128,64]
        int row = u >> 1, d = (u & 1) * 32 + lane;
        float s = 0.f;
        #pragma unroll 8
        for (int i = 0; i < 64; i++)
            s = fmaf(__ldg(cw1 + row * 128 + 64 + i), __ldg(mhw + i * 64 + d), s);
        g_Wp[row * 64 + d] = s;
    } else if (gw < 2564) {
        int row = (gw - 2560) * 32 + lane;  // b'
        float s = __ldg(cb1 + row);
        #pragma unroll 8
        for (int i = 0; i < 64; i++)
            s = fmaf(__ldg(cw1 + row * 128 + 64 + i), __ldg(mhb + i), s);
        g_bp[row] = s;
    }
    gsync();

    // ===== S2: stage-1 norm coefficients (warp/channel) + Sq/Sk strips =====
    if (gw < 128) {
        const float* src = (gw < 64) ? (g_q + gw * NN) : (g_k + (gw - 64) * NN);
        float s = 0.f, s2 = 0.f;
        #pragma unroll
        for (int j = 0; j < 24; j++) {
            float x = src[lane + j * 32];
            s += x; s2 += x * x;
        }
        s = wsum(s); s2 = wsum(s2);
        if (lane == 0) {
            float m = s * (1.f / NN);
            float v = s2 * (1.f / NN) - m * m;
            float si = rsqrtf(v + 1e-3f);
            float vn = v * si * si;
            float sb = rsqrtf(vn + 1e-5f);
            float scale = si * sb * __ldg(bn1g + gw);
            g_nc1[gw] = make_float2(scale, -m * scale + __ldg(bn1b + gw));
        }
    } else if (gw < 176) {
        int u = gw - 128;
        int half = u / 24;
        int n = (u % 24) * 32 + lane;
        const float* X = half ? g_k : g_q;
        float s = 0.f;
        #pragma unroll 8
        for (int i = 0; i < 64; i++)
            s = fmaf(__ldg(shw + half * 64 + i), __ldg(X + i * NN + n), s);
        (half ? g_Sk : g_Sq)[n] = s;
    }
    gsync();

    // ===== S3: A = sw1[:,:64]@relu(norm q); B = sw1[:,64:]@relu(norm k)+sb1 =====
    if (gw < 3072) {
        int half = gw / 1536, rem = gw % 1536;
        int rp = rem / 24, cb = rem % 24;
        int c = cb * 32 + lane;
        int r0 = rp * 2;
        const float* X = half ? g_k : g_q;
        float a0 = 0.f, a1 = 0.f;
        #pragma unroll 8
        for (int i = 0; i < 64; i++) {
            float2 nc = __ldg(g_nc1 + half * 64 + i);
            float x = fmaxf(fmaf(nc.x, __ldg(X + i * NN + c), nc.y), 0.f);
            a0 = fmaf(__ldg(sw1 + r0 * 128 + half * 64 + i), x, a0);
            a1 = fmaf(__ldg(sw1 + (r0 + 1) * 128 + half * 64 + i), x, a1);
        }
        if (half == 0) {
            g_A[r0 * NN + c] = a0;
            g_A[(r0 + 1) * NN + c] = a1;
        } else {
            g_B[r0 * NN + c] = a0 + __ldg(sb1 + r0);
            g_B[(r0 + 1) * NN + c] = a1 + __ldg(sb1 + r0 + 1);
        }
    }
    gsync();

    // ===== S4: stage-2 norm coefficients (separable stats, warp/channel) =====
    if (gw < 128) {
        float sA = 0.f, qA = 0.f, sB = 0.f, qB = 0.f;
        #pragma unroll
        for (int j = 0; j < 24; j++) {
            float a = g_A[gw * NN + lane + j * 32];
            float b = g_B[gw * NN + lane + j * 32];
            sA += a; qA += a * a; sB += b; qB += b * b;
        }
        sA = wsum(sA); qA = wsum(qA); sB = wsum(sB); qB = wsum(qB);
        if (lane == 0) {
            float mA = sA * (1.f / NN), mB = sB * (1.f / NN);
            float vA = qA * (1.f / NN) - mA * mA;
            float vB = qB * (1.f / NN) - mB * mB;
            float m2 = mA + mB, v2 = vA + vB;
            float si = rsqrtf(v2 + 1e-3f);
            float vn = v2 * si * si;
            float sb = rsqrtf(vn + 1e-5f);
            float scale = si * sb * __ldg(bn2g + gw);
            g_nc2[gw] = make_float2(scale, -m2 * scale + __ldg(bn2b + gw));
        }
    }
    gsync();

    // ===== S5: score_pre, 64x64 tiles (144 tiles over 128 blocks) =====
    {
        if (tid < 128) { sm.sc.scb[tid] = g_nc2[tid]; sm.sc.w2s[tid] = __ldg(sw2 + tid); }
        float cc = __ldg(sb2) + __ldg(shb);
        int tx = tid & 15, ty = tid >> 4;   // tx: 4 m, ty: 1 n (0..63)
        for (int t = vb; t < 144; t += G) {
            int n0 = (t / 12) * 64, m0 = (t % 12) * 64;
            __syncthreads();
            if (tid < 64) sm.sc.Sqs[tid] = g_Sq[n0 + tid];
            else if (tid < 128) sm.sc.Sks[tid - 64] = g_Sk[m0 + tid - 64];
            float acc[4] = {};
            #pragma unroll
            for (int ch = 0; ch < 2; ch++) {
                __syncthreads();
                {   // fill As/Bs (64 o x 64 col each), one float4 per thread per array
                    int o = tid >> 4, j4 = (tid & 15) << 2;
                    int og = ch * 64 + o;
                    float2 sb = sm.sc.scb[og];
                    float4 a = *(const float4*)&g_A[og * NN + n0 + j4];
                    a.x = fmaf(sb.x, a.x, sb.y); a.y = fmaf(sb.x, a.y, sb.y);
                    a.z = fmaf(sb.x, a.z, sb.y); a.w = fmaf(sb.x, a.w, sb.y);
                    *(float4*)&sm.sc.As[o * 64 + j4] = a;
                    float4 b = *(const float4*)&g_B[og * NN + m0 + j4];
                    b.x *= sb.x; b.y *= sb.x; b.z *= sb.x; b.w *= sb.x;
                    *(float4*)&sm.sc.Bs[o * 64 + j4] = b;
                }
                __syncthreads();
                #pragma unroll 4
                for (int o = 0; o < 64; o++) {
                    float a = sm.sc.As[o * 64 + ty];
                    float4 b = *(const float4*)&sm.sc.Bs[o * 64 + tx * 4];
                    float w = sm.sc.w2s[ch * 64 + o];
                    acc[0] = fmaf(w, fmaxf(a + b.x, 0.f), acc[0]);
                    acc[1] = fmaf(w, fmaxf(a + b.y, 0.f), acc[1]);
                    acc[2] = fmaf(w, fmaxf(a + b.z, 0.f), acc[2]);
                    acc[3] = fmaf(w, fmaxf(a + b.w, 0.f), acc[3]);
                }
            }
            __syncthreads();
            float sq = sm.sc.Sqs[ty] + cc;
            float4 o4;
            o4.x = acc[0] + sq + sm.sc.Sks[tx * 4 + 0];
            o4.y = acc[1] + sq + sm.sc.Sks[tx * 4 + 1];
            o4.z = acc[2] + sq + sm.sc.Sks[tx * 4 + 2];
            o4.w = acc[3] + sq + sm.sc.Sks[tx * 4 + 3];
            *(float4*)&out_score[(n0 + ty) * NN + m0 + tx * 4] = o4;
        }
    }
    gsync();

    // ===== S6: softmax (warp per row), in place =====
    if (gw < 768) {
        float* p = out_score + gw * NN;
        float v[24];
        float mx = -1e30f;
        #pragma unroll
        for (int i = 0; i < 24; i++) { v[i] = p[lane + i * 32]; mx = fmaxf(mx, v[i]); }
        #pragma unroll
        for (int o = 16; o; o >>= 1) mx = fmaxf(mx, __shfl_xor_sync(0xffffffffu, mx, o));
        float s = 0.f;
        #pragma unroll
        for (int i = 0; i < 24; i++) { v[i] = __expf(v[i] - mx); s += v[i]; }
        s = wsum(s);
        float inv = 1.f / s;
        #pragma unroll
        for (int i = 0; i < 24; i++) p[lane + i * 32] = v[i] * inv;
    }
    gsync();

    // ===== S7: av partials (48 n-tiles of 16 x 2 m-halves = 96 block units) =====
    if (vb < 96) {
        int nt = vb >> 1, ks = vb & 1;
        int n0 = nt * 16, mbase = ks * 384;
        int d0 = (lane) * 2, n = (tid >> 5) & 15, half = tid >> 9;
        float a0 = 0.f, a1 = 0.f;
        for (int c4 = 0; c4 < 6; c4++) {
            int mb = mbase + c4 * 64;
            #pragma unroll
            for (int idx = tid; idx < 4096; idx += T)
                sm.av.Vs[idx] = g_vT[(mb + (idx >> 6)) * 64 + (idx & 63)];
            sm.av.Ps[tid] = out_score[(n0 + (tid >> 6)) * NN + mb + (tid & 63)];
            __syncthreads();
            int m0 = half * 32;
            #pragma unroll 8
            for (int m = 0; m < 32; m++) {
                float2 vv = *(const float2*)&sm.av.Vs[(m0 + m) * 64 + d0];
                float p = sm.av.Ps[n * 64 + m0 + m];
                a0 = fmaf(p, vv.x, a0);
                a1 = fmaf(p, vv.y, a1);
            }
            __syncthreads();
        }
        if (half == 1) {
            sm.av.red[(tid - 512) * 2]     = a0;
            sm.av.red[(tid - 512) * 2 + 1] = a1;
        }
        __syncthreads();
        if (half == 0) {
            a0 += sm.av.red[tid * 2];
            a1 += sm.av.red[tid * 2 + 1];
            g_avp[ks * (64 * NN) + d0 * NN + n0 + n]       = a0;
            g_avp[ks * (64 * NN) + (d0 + 1) * NN + n0 + n] = a1;
        }
    }
    gsync();

    // ===== S8: g1 = cw1[:,:64]@desc1 + W'@(avp0+avp1) + b' =====
    if (gw < 1536) {
        int rp = gw / 24, cb = gw % 24;
        int c = cb * 32 + lane;
        int r0 = rp * 2;
        float a0 = 0.f, a1 = 0.f;
        #pragma unroll 8
        for (int i = 0; i < 64; i++) {
            float x = __ldg(desc1 + i * NN + c);
            a0 = fmaf(__ldg(cw1 + r0 * 128 + i), x, a0);
            a1 = fmaf(__ldg(cw1 + (r0 + 1) * 128 + i), x, a1);
        }
        #pragma unroll 8
        for (int i = 0; i < 64; i++) {
            float x = __ldg(g_avp + i * NN + c) + __ldg(g_avp + 64 * NN + i * NN + c);
            a0 = fmaf(__ldg(g_Wp + r0 * 64 + i), x, a0);
            a1 = fmaf(__ldg(g_Wp + (r0 + 1) * 64 + i), x, a1);
        }
        g_g1[r0 * NN + c] = a0 + __ldg(g_bp + r0);
        g_g1[(r0 + 1) * NN + c] = a1 + __ldg(g_bp + r0 + 1);
    }
    gsync();

    // ===== S9: bnorm1d coefficients (warp/channel) =====
    if (gw < 128) {
        float s = 0.f, s2 = 0.f;
        #pragma unroll
        for (int j = 0; j < 24; j++) {
            float x = g_g1[gw * NN + lane + j * 32];
            s += x; s2 += x * x;
        }
        s = wsum(s); s2 = wsum(s2);
        if (lane == 0) {
            float m = s * (1.f / NN);
            float v = s2 * (1.f / NN) - m * m;
            float scale = rsqrtf(v + 1e-5f) * __ldg(cbg + gw);
            g_ncc[gw] = make_float2(scale, -m * scale + __ldg(cbb + gw));
        }
    }
    gsync();

    // ===== S10: out_desc = desc1 + cw2 @ relu(norm(g1)) + cb2 =====
    if (gw < 768) {
        int rp = gw / 24, cb = gw % 24;
        int c = cb * 32 + lane;
        int r0 = rp * 2;
        float a0 = 0.f, a1 = 0.f;
        #pragma unroll 8
        for (int i = 0; i < 128; i++) {
            float2 nc = __ldg(g_ncc + i);
            float x = fmaxf(fmaf(nc.x, __ldg(g_g1 + i * NN + c), nc.y), 0.f);
            a0 = fmaf(__ldg(cw2 + r0 * 128 + i), x, a0);
            a1 = fmaf(__ldg(cw2 + (r0 + 1) * 128 + i), x, a1);
        }
        out_desc[r0 * NN + c] = a0 + __ldg(cb2 + r0) + __ldg(desc1 + r0 * NN + c);
        out_desc[(r0 + 1) * NN + c] = a1 + __ldg(cb2 + r0 + 1) + __ldg(desc1 + (r0 + 1) * NN + c);
    }
}

// ---------------- launch ----------------
extern "C" void kernel_launch(void* const* d_in, const int* in_sizes, int n_in,
                              void* d_out, int out_size)
{
    const float* desc1 = (const float*)d_in[0];
    const float* desc2 = (const float*)d_in[1];
    const float* qw  = (const float*)d_in[2];  const float* qb  = (const float*)d_in[3];
    const float* kw  = (const float*)d_in[4];  const float* kb  = (const float*)d_in[5];
    const float* vw  = (const float*)d_in[6];  const float* vb  = (const float*)d_in[7];
    const float* mhw = (const float*)d_in[8];  const float* mhb = (const float*)d_in[9];
    const float* cw1 = (const float*)d_in[10]; const float* cb1 = (const float*)d_in[11];
    const float* cbg = (const float*)d_in[12]; const float* cbb = (const float*)d_in[13];
    const float* cw2 = (const float*)d_in[14]; const float* cb2 = (const float*)d_in[15];
    const float* shw = (const float*)d_in[16]; const float* shb = (const float*)d_in[17];
    const float* bn1g = (const float*)d_in[18]; const float* bn1b = (const float*)d_in[19];
    const float* sw1 = (const float*)d_in[20]; const float* sb1 = (const float*)d_in[21];
    const float* bn2g = (const float*)d_in[22]; const float* bn2b = (const float*)d_in[23];
    const float* sw2 = (const float*)d_in[24]; const float* sb2 = (const float*)d_in[25];

    float* out = (float*)d_out;
    float* out_desc  = out;
    float* out_score = out + 64 * NN;

    k_fused<<<G, T>>>(desc1, desc2, qw, qb, kw, kb, vw, vb, mhw, mhb,
                      cw1, cb1, cbg, cbb, cw2, cb2, shw, shb,
                      bn1g, bn1b, sw1, sb1, bn2g, bn2b, sw2, sb2,
                      out_desc, out_score);
}

// round 7
// speedup vs baseline: 1.2328x; 1.2328x over previous
#include <cuda_runtime.h>
#include <math.h>

#define NN 768

// ---------------- scratch ----------------
__device__ float g_q[64*NN], g_k[64*NN], g_vT[NN*64];
__device__ float g_A[128*NN], g_B[128*NN];
__device__ float2 g_nc1[128], g_nc2[128], g_ncc[128];
__device__ float g_Sq[NN], g_Sk[NN];
__device__ float g_avp[4*64*NN], g_g1[128*NN];
__device__ float g_Wp[128*64], g_bp[128];

// ---------------- helpers ----------------
__device__ __forceinline__ float bsum_buf(float v, volatile float* sb) {
    #pragma unroll
    for (int o = 16; o; o >>= 1) v += __shfl_xor_sync(0xffffffffu, v, o);
    if ((threadIdx.x & 31) == 0) sb[threadIdx.x >> 5] = v;
    __syncthreads();
    if (threadIdx.x == 0) {
        float s = sb[0];
        #pragma unroll
        for (int i = 1; i < 8; i++) s += sb[i];
        sb[0] = s;
    }
    __syncthreads();
    return sb[0];
}

// wT[i*16+r] = W[(o0+r)*ldw + koff + i]
__device__ __forceinline__ void fill_W16(float* wT, const float* __restrict__ W,
                                         int ldw, int o0, int koff) {
    for (int v = threadIdx.x; v < 1024; v += 256) {
        int i = v >> 4, r = v & 15;
        wT[v] = W[(o0 + r) * ldw + koff + i];
    }
}

// 16 rows x 128 cols, X streamed from global. acc[8].
__device__ __forceinline__ void gemm16d(const float* __restrict__ X, int c0,
                                        const float* wT, float acc[8]) {
    int c = threadIdx.x & 127, rg = threadIdx.x >> 7;
    const float* xp = X + c0 + c;
    const float* wp = wT + rg * 8;
    #pragma unroll 8
    for (int i = 0; i < 64; i++) {
        float x = __ldg(xp + i * NN);
        float4 w0 = *(const float4*)(wp + i * 16);
        float4 w1 = *(const float4*)(wp + i * 16 + 4);
        acc[0] = fmaf(w0.x, x, acc[0]); acc[1] = fmaf(w0.y, x, acc[1]);
        acc[2] = fmaf(w0.z, x, acc[2]); acc[3] = fmaf(w0.w, x, acc[3]);
        acc[4] = fmaf(w1.x, x, acc[4]); acc[5] = fmaf(w1.y, x, acc[5]);
        acc[6] = fmaf(w1.z, x, acc[6]); acc[7] = fmaf(w1.w, x, acc[7]);
    }
}

// Same, applying relu(nb[i].x * x + nb[i].y) on load.
__device__ __forceinline__ void gemm16d_norm(const float* __restrict__ X, int c0,
                                             const float* wT, const float2* nb,
                                             float acc[8]) {
    int c = threadIdx.x & 127, rg = threadIdx.x >> 7;
    const float* xp = X + c0 + c;
    const float* wp = wT + rg * 8;
    #pragma unroll 8
    for (int i = 0; i < 64; i++) {
        float2 sb = nb[i];
        float x = fmaxf(fmaf(sb.x, __ldg(xp + i * NN), sb.y), 0.f);
        float4 w0 = *(const float4*)(wp + i * 16);
        float4 w1 = *(const float4*)(wp + i * 16 + 4);
        acc[0] = fmaf(w0.x, x, acc[0]); acc[1] = fmaf(w0.y, x, acc[1]);
        acc[2] = fmaf(w0.z, x, acc[2]); acc[3] = fmaf(w0.w, x, acc[3]);
        acc[4] = fmaf(w1.x, x, acc[4]); acc[5] = fmaf(w1.y, x, acc[5]);
        acc[6] = fmaf(w1.z, x, acc[6]); acc[7] = fmaf(w1.w, x, acc[7]);
    }
}

// X = sum of 4 split-k partials at stride S.
template<int S>
__device__ __forceinline__ void gemm16d_s4(const float* __restrict__ X, int c0,
                                           const float* wT, float acc[8]) {
    int c = threadIdx.x & 127, rg = threadIdx.x >> 7;
    const float* xp = X + c0 + c;
    const float* wp = wT + rg * 8;
    #pragma unroll 4
    for (int i = 0; i < 64; i++) {
        float x = (__ldg(xp + i * NN) + __ldg(xp + i * NN + S)) +
                  (__ldg(xp + i * NN + 2 * S) + __ldg(xp + i * NN + 3 * S));
        float4 w0 = *(const float4*)(wp + i * 16);
        float4 w1 = *(const float4*)(wp + i * 16 + 4);
        acc[0] = fmaf(w0.x, x, acc[0]); acc[1] = fmaf(w0.y, x, acc[1]);
        acc[2] = fmaf(w0.z, x, acc[2]); acc[3] = fmaf(w0.w, x, acc[3]);
        acc[4] = fmaf(w1.x, x, acc[4]); acc[5] = fmaf(w1.y, x, acc[5]);
        acc[6] = fmaf(w1.z, x, acc[6]); acc[7] = fmaf(w1.w, x, acc[7]);
    }
}

// ---------------- kernels ----------------

// q,k,v convs (v transposed) + fused W' = cw1[:,64:]@mhw, b'. Grid 89 x 256.
__global__ void k_qkv(const float* __restrict__ d1, const float* __restrict__ d2,
                      const float* __restrict__ qw, const float* __restrict__ qb,
                      const float* __restrict__ kw, const float* __restrict__ kb,
                      const float* __restrict__ vw, const float* __restrict__ vb,
                      const float* __restrict__ mhw, const float* __restrict__ mhb,
                      const float* __restrict__ cw1, const float* __restrict__ cb1)
{
    __shared__ float wT[64 * 16];
    int b = blockIdx.x;
    int tid = threadIdx.x;
    if (b < 72) {
        int grp = b / 24, lb = b % 24;
        int o0 = (lb / 6) * 16, c0 = (lb % 6) * 128;
        const float *W, *X, *Bb;
        if (grp == 0)      { W = qw; X = d1; Bb = qb; }
        else if (grp == 1) { W = kw; X = d2; Bb = kb; }
        else               { W = vw; X = d2; Bb = vb; }
        fill_W16(wT, W, 64, o0, 0);
        __syncthreads();
        float acc[8] = {};
        gemm16d(X, c0, wT, acc);
        int c = tid & 127, rg = tid >> 7;
        int obase = o0 + rg * 8;
        if (grp < 2) {
            float* Y = (grp == 0) ? g_q : g_k;
            #pragma unroll
            for (int r = 0; r < 8; r++)
                Y[(obase + r) * NN + c0 + c] = acc[r] + Bb[obase + r];
        } else {
            int n = c0 + c;
            float4 v0, v1;
            v0.x = acc[0] + Bb[obase + 0]; v0.y = acc[1] + Bb[obase + 1];
            v0.z = acc[2] + Bb[obase + 2]; v0.w = acc[3] + Bb[obase + 3];
            v1.x = acc[4] + Bb[obase + 4]; v1.y = acc[5] + Bb[obase + 5];
            v1.z = acc[6] + Bb[obase + 6]; v1.w = acc[7] + Bb[obase + 7];
            *(float4*)&g_vT[n * 64 + obase]     = v0;
            *(float4*)&g_vT[n * 64 + obase + 4] = v1;
        }
    } else if (b < 88) {
        // W'[row, d] = sum_i cw1[row, 64+i] * mhw[i, d]; 8 rows per block.
        int r0 = (b - 72) * 8;
        int d = tid & 63, rg = tid >> 6;            // 4 groups x 2 rows
        int row = r0 + rg * 2;
        float a0 = 0.f, a1 = 0.f;
        #pragma unroll 8
        for (int i = 0; i < 64; i++) {
            float x = __ldg(mhw + i * 64 + d);
            a0 = fmaf(__ldg(cw1 + row * 128 + 64 + i), x, a0);
            a1 = fmaf(__ldg(cw1 + (row + 1) * 128 + 64 + i), x, a1);
        }
        g_Wp[row * 64 + d] = a0;
        g_Wp[(row + 1) * 64 + d] = a1;
    } else {
        if (tid < 128) {
            float s = __ldg(cb1 + tid);
            #pragma unroll 8
            for (int i = 0; i < 64; i++)
                s = fmaf(__ldg(cw1 + tid * 128 + 64 + i), __ldg(mhb + i), s);
            g_bp[tid] = s;
        }
    }
}

// blocks 0..127: stage-1 norm coefficients; 128..139: Sq/Sk strips. Grid 140.
__global__ void k_stats1(const float* __restrict__ bn1g, const float* __restrict__ bn1b,
                         const float* __restrict__ shw)
{
    int b = blockIdx.x;
    int tid = threadIdx.x;
    if (b < 128) {
        const float* src = (b < 64) ? (g_q + b * NN) : (g_k + (b - 64) * NN);
        float s = 0.f, s2 = 0.f;
        #pragma unroll
        for (int j = 0; j < 3; j++) {
            float x = src[tid + j * 256];
            s += x; s2 += x * x;
        }
        __shared__ float r1[8], r2[8];
        s  = bsum_buf(s,  r1);
        s2 = bsum_buf(s2, r2);
        if (tid == 0) {
            float m = s * (1.f / NN);
            float v = s2 * (1.f / NN) - m * m;
            float si = rsqrtf(v + 1e-3f);
            float vb = v * si * si;
            float sb = rsqrtf(vb + 1e-5f);
            float scale = si * sb * bn1g[b];
            g_nc1[b] = make_float2(scale, -m * scale + bn1b[b]);
        }
    } else {
        int j = b - 128;
        int half = j / 6, cb = j % 6;
        int n = cb * 128 + (tid & 127);
        int ch = tid >> 7;
        const float* src = half ? g_k : g_q;
        const float* w = shw + half * 64 + ch * 32;
        const float* xp = src + ch * 32 * NN + n;
        float s = 0.f;
        #pragma unroll 8
        for (int i = 0; i < 32; i++) s = fmaf(__ldg(w + i), __ldg(xp + i * NN), s);
        __shared__ float red[256];
        red[tid] = s;
        __syncthreads();
        if (tid < 128) {
            float* dst = half ? g_Sk : g_Sq;
            dst[n] = red[tid] + red[tid + 128];
        }
    }
}

// A = sw1[:,:64]@relu(norm q); B = sw1[:,64:]@relu(norm k)+sb1. Grid 96 x 256.
__global__ void k_AB(const float* __restrict__ w1, const float* __restrict__ b1)
{
    __shared__ float wT[64 * 16];
    __shared__ float2 nb[64];
    int b = blockIdx.x;
    int half = b / 48, lb = b % 48;
    int o0 = (lb / 6) * 16, c0 = (lb % 6) * 128;
    const float* X = half ? g_k : g_q;
    if (threadIdx.x < 64) nb[threadIdx.x] = g_nc1[half * 64 + threadIdx.x];
    fill_W16(wT, w1, 128, o0, half ? 64 : 0);
    __syncthreads();
    float acc[8] = {};
    gemm16d_norm(X, c0, wT, nb, acc);
    int c = threadIdx.x & 127, rg = threadIdx.x >> 7;
    int obase = o0 + rg * 8;
    if (half == 0) {
        #pragma unroll
        for (int r = 0; r < 8; r++)
            g_A[(obase + r) * NN + c0 + c] = acc[r];
    } else {
        #pragma unroll
        for (int r = 0; r < 8; r++)
            g_B[(obase + r) * NN + c0 + c] = acc[r] + b1[obase + r];
    }
}

// Stage-2 composite norm coefficients. Grid 128 x 256.
__global__ void k_stats2(const float* __restrict__ bn2g, const float* __restrict__ bn2b)
{
    int o = blockIdx.x;
    int tid = threadIdx.x;
    float sA = 0.f, qA = 0.f, sB = 0.f, qB = 0.f;
    #pragma unroll
    for (int j = 0; j < 3; j++) {
        float a = g_A[o * NN + tid + j * 256];
        float b = g_B[o * NN + tid + j * 256];
        sA += a; qA += a * a; sB += b; qB += b * b;
    }
    __shared__ float r1[8], r2[8], r3[8], r4[8];
    sA = bsum_buf(sA, r1); qA = bsum_buf(qA, r2);
    sB = bsum_buf(sB, r3); qB = bsum_buf(qB, r4);
    if (tid == 0) {
        float mA = sA * (1.f / NN), mB = sB * (1.f / NN);
        float vA = qA * (1.f / NN) - mA * mA;
        float vB = qB * (1.f / NN) - mB * mB;
        float m2 = mA + mB, v2 = vA + vB;
        float si = rsqrtf(v2 + 1e-3f);
        float vb = v2 * si * si;
        float sb = rsqrtf(vb + 1e-5f);
        float scale = si * sb * bn2g[o];
        g_nc2[o] = make_float2(scale, -m2 * scale + bn2b[o]);
    }
}

// score_pre, 64x64 tiles, 512 threads. Grid (12,12).
__global__ void __launch_bounds__(512)
k_score(const float* __restrict__ w2, const float* __restrict__ b2p,
        const float* __restrict__ bsp, float* __restrict__ out)
{
    __shared__ float As[64 * 64];
    __shared__ float Bs[64 * 64];
    __shared__ float2 scb[128];
    __shared__ float w2s[128];
    __shared__ float Sqs[64], Sks[64];
    int tid = threadIdx.x;
    int n0 = blockIdx.y * 64, m0 = blockIdx.x * 64;
    if (tid < 128) { scb[tid] = g_nc2[tid]; w2s[tid] = w2[tid]; }
    else if (tid < 192) Sqs[tid - 128] = g_Sq[n0 + tid - 128];
    else if (tid < 256) Sks[tid - 192] = g_Sk[m0 + tid - 192];
    __syncthreads();

    int tx = tid & 15, ty = tid >> 4;
    float acc[2][4] = {};
    #pragma unroll
    for (int ch = 0; ch < 2; ch++) {
        #pragma unroll
        for (int v = tid; v < 1024; v += 512) {
            int o = v >> 4, t4 = (v & 15) << 2;
            int og = ch * 64 + o;
            float2 sb = scb[og];
            float4 a = *(const float4*)&g_A[og * NN + n0 + t4];
            a.x = fmaf(sb.x, a.x, sb.y); a.y = fmaf(sb.x, a.y, sb.y);
            a.z = fmaf(sb.x, a.z, sb.y); a.w = fmaf(sb.x, a.w, sb.y);
            *(float4*)&As[o * 64 + t4] = a;
            float4 bv = *(const float4*)&g_B[og * NN + m0 + t4];
            bv.x *= sb.x; bv.y *= sb.x; bv.z *= sb.x; bv.w *= sb.x;
            *(float4*)&Bs[o * 64 + t4] = bv;
        }
        __syncthreads();
        #pragma unroll 4
        for (int o = 0; o < 64; o++) {
            float2 a = *(const float2*)&As[o * 64 + ty * 2];
            float4 bv = *(const float4*)&Bs[o * 64 + tx * 4];
            float w = w2s[ch * 64 + o];
            acc[0][0] = fmaf(w, fmaxf(a.x + bv.x, 0.f), acc[0][0]);
            acc[0][1] = fmaf(w, fmaxf(a.x + bv.y, 0.f), acc[0][1]);
            acc[0][2] = fmaf(w, fmaxf(a.x + bv.z, 0.f), acc[0][2]);
            acc[0][3] = fmaf(w, fmaxf(a.x + bv.w, 0.f), acc[0][3]);
            acc[1][0] = fmaf(w, fmaxf(a.y + bv.x, 0.f), acc[1][0]);
            acc[1][1] = fmaf(w, fmaxf(a.y + bv.y, 0.f), acc[1][1]);
            acc[1][2] = fmaf(w, fmaxf(a.y + bv.z, 0.f), acc[1][2]);
            acc[1][3] = fmaf(w, fmaxf(a.y + bv.w, 0.f), acc[1][3]);
        }
        __syncthreads();
    }
    float cc = __ldg(b2p) + __ldg(bsp);
    #pragma unroll
    for (int rn = 0; rn < 2; rn++) {
        int n = n0 + ty * 2 + rn;
        float sq = Sqs[ty * 2 + rn] + cc;
        float4 o4;
        o4.x = acc[rn][0] + sq + Sks[tx * 4 + 0];
        o4.y = acc[rn][1] + sq + Sks[tx * 4 + 1];
        o4.z = acc[rn][2] + sq + Sks[tx * 4 + 2];
        o4.w = acc[rn][3] + sq + Sks[tx * 4 + 3];
        *(float4*)&out[n * NN + m0 + tx * 4] = o4;
    }
}

// warp-per-row softmax, in place. Grid 96 x 256.
__global__ void k_softmax(float* __restrict__ score)
{
    int row = blockIdx.x * 8 + (threadIdx.x >> 5);
    int lane = threadIdx.x & 31;
    float* p = score + row * NN;
    float v[24];
    float mx = -1e30f;
    #pragma unroll
    for (int i = 0; i < 24; i++) { v[i] = p[lane + i * 32]; mx = fmaxf(mx, v[i]); }
    #pragma unroll
    for (int o = 16; o; o >>= 1) mx = fmaxf(mx, __shfl_xor_sync(0xffffffffu, mx, o));
    float s = 0.f;
    #pragma unroll
    for (int i = 0; i < 24; i++) { v[i] = __expf(v[i] - mx); s += v[i]; }
    #pragma unroll
    for (int o = 16; o; o >>= 1) s += __shfl_xor_sync(0xffffffffu, s, o);
    float inv = 1.f / s;
    #pragma unroll
    for (int i = 0; i < 24; i++) p[lane + i * 32] = v[i] * inv;
}

// av partials: 48 n-tiles x 4 k-splits = 192 x 256.
__global__ void k_av(const float* __restrict__ score)
{
    int bx = blockIdx.x;
    int nt = bx % 48, ks = bx / 48;
    int n0 = nt * 16;
    int tid = threadIdx.x;
    __shared__ float Vs[64][64];
    __shared__ float Ps[16][64];
    int d0  = (tid & 31) * 2;
    int nl0 = (tid >> 5) * 2;
    float a00 = 0.f, a01 = 0.f, a10 = 0.f, a11 = 0.f;
    for (int c = 0; c < 3; c++) {
        int mb = ks * 192 + c * 64;
        for (int idx = tid; idx < 64 * 64; idx += 256)
            Vs[idx >> 6][idx & 63] = g_vT[(mb + (idx >> 6)) * 64 + (idx & 63)];
        for (int idx = tid; idx < 16 * 64; idx += 256)
            Ps[idx >> 6][idx & 63] = score[(n0 + (idx >> 6)) * NN + mb + (idx & 63)];
        __syncthreads();
        #pragma unroll 4
        for (int m = 0; m < 64; m++) {
            float2 vv = *(const float2*)&Vs[m][d0];
            float p0 = Ps[nl0][m], p1 = Ps[nl0 + 1][m];
            a00 = fmaf(p0, vv.x, a00); a01 = fmaf(p0, vv.y, a01);
            a10 = fmaf(p1, vv.x, a10); a11 = fmaf(p1, vv.y, a11);
        }
        __syncthreads();
    }
    float* dst = g_avp + ks * (64 * NN);
    dst[d0 * NN + n0 + nl0]           = a00;
    dst[(d0 + 1) * NN + n0 + nl0]     = a01;
    dst[d0 * NN + n0 + nl0 + 1]       = a10;
    dst[(d0 + 1) * NN + n0 + nl0 + 1] = a11;
}

// g1 = cw1[:,:64]@desc1 + W'@(sum of 4 av partials) + b'. Grid 48 x 256.
__global__ void k_g1(const float* __restrict__ cw1, const float* __restrict__ desc1)
{
    __shared__ float wT[64 * 16];
    int lb = blockIdx.x;
    int o0 = (lb / 6) * 16, c0 = (lb % 6) * 128;
    float acc[8] = {};
    fill_W16(wT, cw1, 128, o0, 0);
    __syncthreads();
    gemm16d(desc1, c0, wT, acc);
    __syncthreads();
    fill_W16(wT, g_Wp, 64, o0, 0);
    __syncthreads();
    gemm16d_s4<64 * NN>(g_avp, c0, wT, acc);
    int c = threadIdx.x & 127, rg = threadIdx.x >> 7;
    int obase = o0 + rg * 8;
    #pragma unroll
    for (int r = 0; r < 8; r++)
        g_g1[(obase + r) * NN + c0 + c] = acc[r] + g_bp[obase + r];
}

// bnorm1d coefficients. Grid 128 x 256.
__global__ void k_bnstats(const float* __restrict__ cbg, const float* __restrict__ cbb)
{
    int o = blockIdx.x;
    int tid = threadIdx.x;
    float s = 0.f, s2 = 0.f;
    #pragma unroll
    for (int j = 0; j < 3; j++) {
        float x = g_g1[o * NN + tid + j * 256];
        s += x; s2 += x * x;
    }
    __shared__ float r1[8], r2[8];
    s = bsum_buf(s, r1); s2 = bsum_buf(s2, r2);
    if (tid == 0) {
        float m = s * (1.f / NN);
        float v = s2 * (1.f / NN) - m * m;
        float scale = rsqrtf(v + 1e-5f) * cbg[o];
        g_ncc[o] = make_float2(scale, -m * scale + cbb[o]);
    }
}

// out_desc = desc1 + cw2 @ relu(norm(g1)) + cb2. Grid 24 x 256.
__global__ void k_final(const float* __restrict__ cw2, const float* __restrict__ cb2,
                        const float* __restrict__ desc1, float* __restrict__ out)
{
    __shared__ float wT[64 * 16];
    __shared__ float2 nb[64];
    int lb = blockIdx.x;
    int o0 = (lb / 6) * 16, c0 = (lb % 6) * 128;
    float acc[8] = {};
    if (threadIdx.x < 64) nb[threadIdx.x] = g_ncc[threadIdx.x];
    fill_W16(wT, cw2, 128, o0, 0);
    __syncthreads();
    gemm16d_norm(g_g1, c0, wT, nb, acc);
    __syncthreads();
    if (threadIdx.x < 64) nb[threadIdx.x] = g_ncc[64 + threadIdx.x];
    fill_W16(wT, cw2, 128, o0, 64);
    __syncthreads();
    gemm16d_norm(g_g1 + 64 * NN, c0, wT, nb, acc);
    int c = threadIdx.x & 127, rg = threadIdx.x >> 7;
    int obase = o0 + rg * 8;
    #pragma unroll
    for (int r = 0; r < 8; r++)
        out[(obase + r) * NN + c0 + c] =
            acc[r] + cb2[obase + r] + desc1[(obase + r) * NN + c0 + c];
}

// ---------------- launch ----------------
extern "C" void kernel_launch(void* const* d_in, const int* in_sizes, int n_in,
                              void* d_out, int out_size)
{
    const float* desc1 = (const float*)d_in[0];
    const float* desc2 = (const float*)d_in[1];
    const float* qw  = (const float*)d_in[2];  const float* qb  = (const float*)d_in[3];
    const float* kw  = (const float*)d_in[4];  const float* kb  = (const float*)d_in[5];
    const float* vw  = (const float*)d_in[6];  const float* vb  = (const float*)d_in[7];
    const float* mhw = (const float*)d_in[8];  const float* mhb = (const float*)d_in[9];
    const float* cw1 = (const float*)d_in[10]; const float* cb1 = (const float*)d_in[11];
    const float* cbg = (const float*)d_in[12]; const float* cbb = (const float*)d_in[13];
    const float* cw2 = (const float*)d_in[14]; const float* cb2 = (const float*)d_in[15];
    const float* shw = (const float*)d_in[16]; const float* shb = (const float*)d_in[17];
    const float* bn1g = (const float*)d_in[18]; const float* bn1b = (const float*)d_in[19];
    const float* sw1 = (const float*)d_in[20]; const float* sb1 = (const float*)d_in[21];
    const float* bn2g = (const float*)d_in[22]; const float* bn2b = (const float*)d_in[23];
    const float* sw2 = (const float*)d_in[24]; const float* sb2 = (const float*)d_in[25];

    float* out = (float*)d_out;
    float* out_desc  = out;
    float* out_score = out + 64 * NN;

    k_qkv<<<89, 256>>>(desc1, desc2, qw, qb, kw, kb, vw, vb, mhw, mhb, cw1, cb1);
    k_stats1<<<140, 256>>>(bn1g, bn1b, shw);
    k_AB<<<96, 256>>>(sw1, sb1);
    k_stats2<<<128, 256>>>(bn2g, bn2b);
    k_score<<<dim3(12, 12), 512>>>(sw2, sb2, shb, out_score);
    k_softmax<<<96, 256>>>(out_score);
    k_av<<<192, 256>>>(out_score);
    k_g1<<<48, 256>>>(cw1, desc1);
    k_bnstats<<<128, 256>>>(cbg, cbb);
    k_final<<<24, 256>>>(cw2, cb2, desc1, out_desc);
}